// round 1
// baseline (speedup 1.0000x reference)
#include <cuda_runtime.h>
#include <stdint.h>

#define NN 50000
#define NG 256
#define DIM 128
#define NE 800000

// ---------------- scratch (static __device__ => no runtime allocation) ------
__device__ float g_agg [NN * DIM];
__device__ float g_bufA[NN * DIM];
__device__ float g_bufB[NN * DIM];
__device__ int   g_rowptr[NN + 1];
__device__ int   g_cnt[NN];
__device__ int   g_col[NE];
__device__ int   g_gstart[NG + 1];
__device__ int   g_is64;

// ---------------- dtype-agnostic index access -------------------------------
__device__ __forceinline__ long long idx_at(const void* p, long long i) {
    if (g_is64) return ((const long long*)p)[i];
    return (long long)((const int*)p)[i];
}

// ---------------- init: zero counters, assume int64 until disproven ---------
__global__ void k_init() {
    int i = blockIdx.x * blockDim.x + threadIdx.x;
    if (i < NN) g_cnt[i] = 0;
    if (i == 0) g_is64 = 1;
}

// If the edge buffer is int32, the odd 32-bit words are real node ids (mostly
// nonzero). If int64 (values < 2^31, nonnegative), odd words are all zero.
// Only touches the first 2E*4 bytes, which is in-bounds for both layouts.
__global__ void k_detect(const int* __restrict__ ei32, int e2) {
    int i = blockIdx.x * blockDim.x + threadIdx.x;
    int idx = 2 * i + 1;
    if (idx < e2 && ei32[idx] != 0) g_is64 = 0;
}

// ---------------- CSR build --------------------------------------------------
__global__ void k_count(const void* __restrict__ ei, int E) {
    int e = blockIdx.x * blockDim.x + threadIdx.x;
    if (e >= E) return;
    int d = (int)idx_at(ei, (long long)E + e);
    atomicAdd(&g_cnt[d], 1);
}

// single-block exclusive scan over g_cnt -> g_rowptr; re-zeroes g_cnt (cursors)
__global__ void k_scan(int n) {
    __shared__ int warpsum[32];
    __shared__ int s_carry;
    const int t = threadIdx.x;          // 1024 threads
    const int lane = t & 31, w = t >> 5;
    if (t == 0) s_carry = 0;
    __syncthreads();
    for (int base = 0; base < n; base += 1024) {
        int i = base + t;
        int v = (i < n) ? g_cnt[i] : 0;
        int x = v;
        #pragma unroll
        for (int o = 1; o < 32; o <<= 1) {
            int y = __shfl_up_sync(0xFFFFFFFFu, x, o);
            if (lane >= o) x += y;
        }
        if (lane == 31) warpsum[w] = x;
        __syncthreads();
        if (w == 0) {
            int ws = warpsum[lane];
            #pragma unroll
            for (int o = 1; o < 32; o <<= 1) {
                int y = __shfl_up_sync(0xFFFFFFFFu, ws, o);
                if (lane >= o) ws += y;
            }
            warpsum[lane] = ws;          // inclusive warp-total scan
        }
        __syncthreads();
        int excl = x - v + (w > 0 ? warpsum[w - 1] : 0) + s_carry;
        if (i < n) { g_rowptr[i] = excl; g_cnt[i] = 0; }
        __syncthreads();
        if (t == 1023) s_carry = excl + v;
        __syncthreads();
    }
    if (t == 0) g_rowptr[n] = s_carry;
}

__global__ void k_fill(const void* __restrict__ ei, int E) {
    int e = blockIdx.x * blockDim.x + threadIdx.x;
    if (e >= E) return;
    int s = (int)idx_at(ei, e);
    int d = (int)idx_at(ei, (long long)E + e);
    int pos = g_rowptr[d] + atomicAdd(&g_cnt[d], 1);
    g_col[pos] = s;
}

// ---------------- mean aggregation: one warp per destination node -----------
__global__ void k_agg(const float* __restrict__ h) {
    int warp = (blockIdx.x * blockDim.x + threadIdx.x) >> 5;
    int lane = threadIdx.x & 31;
    if (warp >= NN) return;
    int beg = g_rowptr[warp], end = g_rowptr[warp + 1];
    float4 acc = make_float4(0.f, 0.f, 0.f, 0.f);
    int i = beg;
    for (; i + 1 < end; i += 2) {
        int s0 = g_col[i], s1 = g_col[i + 1];
        float4 v0 = *(const float4*)(h + (size_t)s0 * DIM + lane * 4);
        float4 v1 = *(const float4*)(h + (size_t)s1 * DIM + lane * 4);
        acc.x += v0.x + v1.x; acc.y += v0.y + v1.y;
        acc.z += v0.z + v1.z; acc.w += v0.w + v1.w;
    }
    if (i < end) {
        int s0 = g_col[i];
        float4 v0 = *(const float4*)(h + (size_t)s0 * DIM + lane * 4);
        acc.x += v0.x; acc.y += v0.y; acc.z += v0.z; acc.w += v0.w;
    }
    int deg = end - beg;
    float inv = 1.0f / (float)(deg > 0 ? deg : 1);
    float4 o = make_float4(acc.x * inv, acc.y * inv, acc.z * inv, acc.w * inv);
    *(float4*)(g_agg + (size_t)warp * DIM + lane * 4) = o;
}

// ---------------- fused dual GEMM: out = relu(A@Wl + H@Wr + bias) -----------
// BM=64, BN=128(=DIM), K=128 per matrix; 256 threads; TM=8 x TN=4 per thread.
__global__ void __launch_bounds__(256)
k_gemm(const float* __restrict__ A, const float* __restrict__ H,
       const float* __restrict__ Wl, const float* __restrict__ Wr,
       const float* __restrict__ bias, float* __restrict__ out, int M)
{
    __shared__ __align__(16) float sA [64][16];
    __shared__ __align__(16) float sH [64][16];
    __shared__ __align__(16) float sWl[16][128];
    __shared__ __align__(16) float sWr[16][128];

    const int tid = threadIdx.x;
    const int tx  = tid & 31;     // column group (TN=4)
    const int ty  = tid >> 5;     // row group  (TM=8)
    const int row0 = blockIdx.x * 64;

    float acc[8][4];
    #pragma unroll
    for (int i = 0; i < 8; i++)
        #pragma unroll
        for (int j = 0; j < 4; j++) acc[i][j] = 0.f;

    const int lr = tid >> 2;            // 0..63
    const int lc = (tid & 3) * 4;       // 0,4,8,12
    const int gr_load = row0 + lr;
    const bool valid = (gr_load < M);

    for (int kc = 0; kc < 128; kc += 16) {
        float4 va = make_float4(0.f, 0.f, 0.f, 0.f), vh = va;
        if (valid) {
            va = *(const float4*)(A + (size_t)gr_load * 128 + kc + lc);
            vh = *(const float4*)(H + (size_t)gr_load * 128 + kc + lc);
        }
        *(float4*)&sA[lr][lc] = va;
        *(float4*)&sH[lr][lc] = vh;
        #pragma unroll
        for (int t2 = 0; t2 < 2; t2++) {
            int idx = tid + t2 * 256;   // float4 index in [0,512)
            int wr_ = idx >> 5;         // 0..15
            int wc  = (idx & 31) * 4;
            *(float4*)&sWl[wr_][wc] = *(const float4*)(Wl + (size_t)(kc + wr_) * 128 + wc);
            *(float4*)&sWr[wr_][wc] = *(const float4*)(Wr + (size_t)(kc + wr_) * 128 + wc);
        }
        __syncthreads();

        #pragma unroll
        for (int k4 = 0; k4 < 16; k4 += 4) {
            float4 a1[8], a2[8];
            #pragma unroll
            for (int i = 0; i < 8; i++) {
                a1[i] = *(const float4*)&sA[ty * 8 + i][k4];
                a2[i] = *(const float4*)&sH[ty * 8 + i][k4];
            }
            #pragma unroll
            for (int kk = 0; kk < 4; kk++) {
                float4 b1 = *(const float4*)&sWl[k4 + kk][tx * 4];
                float4 b2 = *(const float4*)&sWr[k4 + kk][tx * 4];
                #pragma unroll
                for (int i = 0; i < 8; i++) {
                    float x1 = (kk == 0) ? a1[i].x : (kk == 1) ? a1[i].y : (kk == 2) ? a1[i].z : a1[i].w;
                    float x2 = (kk == 0) ? a2[i].x : (kk == 1) ? a2[i].y : (kk == 2) ? a2[i].z : a2[i].w;
                    acc[i][0] = fmaf(x1, b1.x, fmaf(x2, b2.x, acc[i][0]));
                    acc[i][1] = fmaf(x1, b1.y, fmaf(x2, b2.y, acc[i][1]));
                    acc[i][2] = fmaf(x1, b1.z, fmaf(x2, b2.z, acc[i][2]));
                    acc[i][3] = fmaf(x1, b1.w, fmaf(x2, b2.w, acc[i][3]));
                }
            }
        }
        __syncthreads();
    }

    float4 bv = *(const float4*)(bias + tx * 4);
    #pragma unroll
    for (int i = 0; i < 8; i++) {
        int gr = row0 + ty * 8 + i;
        if (gr < M) {
            float4 o;
            o.x = fmaxf(acc[i][0] + bv.x, 0.f);
            o.y = fmaxf(acc[i][1] + bv.y, 0.f);
            o.z = fmaxf(acc[i][2] + bv.z, 0.f);
            o.w = fmaxf(acc[i][3] + bv.w, 0.f);
            *(float4*)(out + (size_t)gr * 128 + tx * 4) = o;
        }
    }
}

// ---------------- per-graph boundaries (batch is sorted) --------------------
__global__ void k_bounds(const void* __restrict__ batch, int n) {
    int g = blockIdx.x * blockDim.x + threadIdx.x;
    if (g > NG) return;
    int lo = 0, hi = n;
    while (lo < hi) {
        int mid = (lo + hi) >> 1;
        if (idx_at(batch, mid) < (long long)g) lo = mid + 1; else hi = mid;
    }
    g_gstart[g] = lo;
}

// ---------------- meanmax readout: one block per graph ----------------------
__global__ void k_readout(const float* __restrict__ h, float* __restrict__ out) {
    int g = blockIdx.x;
    int c = threadIdx.x;                 // 0..127
    int s = g_gstart[g], e = g_gstart[g + 1];
    float sum = 0.f, mx = 0.f;           // values are post-relu (>=0); empty->0
    for (int n = s; n < e; n++) {
        float v = __ldg(h + (size_t)n * DIM + c);
        sum += v;
        mx = fmaxf(mx, v);
    }
    out[g * (2 * DIM) + c]       = sum / fmaxf((float)(e - s), 1.f);
    out[g * (2 * DIM) + DIM + c] = mx;
}

// ---------------- launcher ---------------------------------------------------
extern "C" void kernel_launch(void* const* d_in, const int* in_sizes, int n_in,
                              void* d_out, int out_size)
{
    const float* x     = (const float*)d_in[0];
    const void*  ei    = d_in[1];
    const void*  batch = d_in[2];
    const float* Wl0 = (const float*)d_in[3];
    const float* bl0 = (const float*)d_in[4];
    const float* Wr0 = (const float*)d_in[5];
    const float* Wl1 = (const float*)d_in[6];
    const float* bl1 = (const float*)d_in[7];
    const float* Wr1 = (const float*)d_in[8];
    const float* Wl2 = (const float*)d_in[9];
    const float* bl2 = (const float*)d_in[10];
    const float* Wr2 = (const float*)d_in[11];
    float* out = (float*)d_out;

    const int N = in_sizes[0] / DIM;     // 50000
    const int E = in_sizes[1] / 2;       // 800000

    float *agg, *bufA, *bufB;
    cudaGetSymbolAddress((void**)&agg,  g_agg);
    cudaGetSymbolAddress((void**)&bufA, g_bufA);
    cudaGetSymbolAddress((void**)&bufB, g_bufB);

    k_init  <<<(NN + 255) / 256, 256>>>();
    k_detect<<<(E + 255) / 256, 256>>>((const int*)ei, 2 * E);
    k_count <<<(E + 255) / 256, 256>>>(ei, E);
    k_scan  <<<1, 1024>>>(N);
    k_fill  <<<(E + 255) / 256, 256>>>(ei, E);

    const int aggGrid  = (NN * 32 + 255) / 256;   // one warp per node
    const int gemmGrid = (N + 63) / 64;

    // layer 0: h = x
    k_agg <<<aggGrid, 256>>>(x);
    k_gemm<<<gemmGrid, 256>>>(agg, x, Wl0, Wr0, bl0, bufA, N);
    // layer 1
    k_agg <<<aggGrid, 256>>>(bufA);
    k_gemm<<<gemmGrid, 256>>>(agg, bufA, Wl1, Wr1, bl1, bufB, N);
    // layer 2
    k_agg <<<aggGrid, 256>>>(bufB);
    k_gemm<<<gemmGrid, 256>>>(agg, bufB, Wl2, Wr2, bl2, bufA, N);

    k_bounds <<<1, 512>>>(batch, N);
    k_readout<<<NG, DIM>>>(bufA, out);
}

// round 2
// speedup vs baseline: 1.1865x; 1.1865x over previous
#include <cuda_runtime.h>
#include <cuda_bf16.h>
#include <stdint.h>

#define NN 50000
#define NG 256
#define DIM 128
#define NE 800000

// ---------------- scratch (static __device__ => no runtime allocation) ------
__device__ float g_agg [NN * DIM];
__device__ float g_bufA[NN * DIM];
__device__ float g_bufB[NN * DIM];
__device__ int   g_rowptr[NN + 1];
__device__ int   g_cnt[NN];
__device__ int   g_col[NE];
__device__ int   g_gstart[NG + 1];
__device__ int   g_is64;
__device__ int   g_bsum[256];
__device__ int   g_boff[256];

// ---------------- dtype-agnostic index access -------------------------------
__device__ __forceinline__ long long idx_at(const void* p, long long i) {
    if (g_is64) return ((const long long*)p)[i];
    return (long long)((const int*)p)[i];
}

// ---------------- init: zero counters, assume int64 until disproven ---------
__global__ void k_init() {
    int i = blockIdx.x * blockDim.x + threadIdx.x;
    if (i < NN) g_cnt[i] = 0;
    if (i == 0) g_is64 = 1;
}

// If edges are int32, odd 32-bit words are real ids (mostly nonzero); if int64
// (nonnegative < 2^31) odd words are all zero.
__global__ void k_detect(const int* __restrict__ ei32, int e2) {
    int i = blockIdx.x * blockDim.x + threadIdx.x;
    int idx = 2 * i + 1;
    if (idx < e2 && ei32[idx] != 0) g_is64 = 0;
}

// ---------------- CSR build --------------------------------------------------
__global__ void k_count(const void* __restrict__ ei, int E) {
    int e = blockIdx.x * blockDim.x + threadIdx.x;
    if (e >= E) return;
    int d = (int)idx_at(ei, (long long)E + e);
    atomicAdd(&g_cnt[d], 1);
}

// block-level exclusive scan helper (256 threads)
__device__ __forceinline__ int blk_excl_scan(int v, int* warpsum) {
    int tid = threadIdx.x, lane = tid & 31, w = tid >> 5;
    int x = v;
    #pragma unroll
    for (int o = 1; o < 32; o <<= 1) {
        int y = __shfl_up_sync(0xFFFFFFFFu, x, o);
        if (lane >= o) x += y;
    }
    if (lane == 31) warpsum[w] = x;
    __syncthreads();
    if (w == 0 && lane < 8) {
        int s = warpsum[lane];
        #pragma unroll
        for (int o = 1; o < 8; o <<= 1) {
            int y = __shfl_up_sync(0xFFu, s, o);
            if (lane >= o) s += y;
        }
        warpsum[lane] = s;   // inclusive scan of warp totals
    }
    __syncthreads();
    return x - v + (w > 0 ? warpsum[w - 1] : 0);
}

// hierarchical scan: per-block sums
__global__ void k_bsum(int n) {
    __shared__ int warpsum[8];
    int i = blockIdx.x * 256 + threadIdx.x;
    int v = (i < n) ? g_cnt[i] : 0;
    int lane = threadIdx.x & 31, w = threadIdx.x >> 5;
    #pragma unroll
    for (int o = 16; o > 0; o >>= 1) v += __shfl_down_sync(0xFFFFFFFFu, v, o);
    if (lane == 0) warpsum[w] = v;
    __syncthreads();
    if (threadIdx.x == 0) {
        int s = 0;
        #pragma unroll
        for (int k = 0; k < 8; k++) s += warpsum[k];
        g_bsum[blockIdx.x] = s;
    }
}

// scan the 196 block sums (single block)
__global__ void k_bscan(int nb, int n) {
    __shared__ int warpsum[8];
    int t = threadIdx.x;
    int v = (t < nb) ? g_bsum[t] : 0;
    int excl = blk_excl_scan(v, warpsum);
    if (t < nb) g_boff[t] = excl;
    if (t == nb - 1) g_rowptr[n] = excl + v;
}

// apply offsets: per-block exclusive scan + boff -> rowptr; re-zero cnt
__global__ void k_rowptr(int n) {
    __shared__ int warpsum[8];
    int i = blockIdx.x * 256 + threadIdx.x;
    int v = (i < n) ? g_cnt[i] : 0;
    int excl = blk_excl_scan(v, warpsum);
    if (i < n) { g_rowptr[i] = g_boff[blockIdx.x] + excl; g_cnt[i] = 0; }
}

__global__ void k_fill(const void* __restrict__ ei, int E) {
    int e = blockIdx.x * blockDim.x + threadIdx.x;
    if (e >= E) return;
    int s = (int)idx_at(ei, e);
    int d = (int)idx_at(ei, (long long)E + e);
    int pos = g_rowptr[d] + atomicAdd(&g_cnt[d], 1);
    g_col[pos] = s;
}

// ---------------- mean aggregation: one warp per destination node -----------
__global__ void k_agg(const float* __restrict__ h, int N) {
    int warp = (blockIdx.x * blockDim.x + threadIdx.x) >> 5;
    int lane = threadIdx.x & 31;
    if (warp >= N) return;
    int beg = g_rowptr[warp], end = g_rowptr[warp + 1];
    float4 acc = make_float4(0.f, 0.f, 0.f, 0.f);
    int i = beg;
    for (; i + 1 < end; i += 2) {
        int s0 = __ldg(&g_col[i]), s1 = __ldg(&g_col[i + 1]);
        float4 v0 = *(const float4*)(h + (size_t)s0 * DIM + lane * 4);
        float4 v1 = *(const float4*)(h + (size_t)s1 * DIM + lane * 4);
        acc.x += v0.x + v1.x; acc.y += v0.y + v1.y;
        acc.z += v0.z + v1.z; acc.w += v0.w + v1.w;
    }
    if (i < end) {
        int s0 = __ldg(&g_col[i]);
        float4 v0 = *(const float4*)(h + (size_t)s0 * DIM + lane * 4);
        acc.x += v0.x; acc.y += v0.y; acc.z += v0.z; acc.w += v0.w;
    }
    int deg = end - beg;
    float inv = 1.0f / (float)(deg > 0 ? deg : 1);
    float4 o = make_float4(acc.x * inv, acc.y * inv, acc.z * inv, acc.w * inv);
    *(float4*)(g_agg + (size_t)warp * DIM + lane * 4) = o;
}

// ---------------- tensor-core fused dual GEMM --------------------------------
// out = relu( A@Wl + H@Wr + bias ), all fp32 in/out, computed as bf16-split
// 3-product MMA (a*b = ahi*bhi + ahi*blo + alo*bhi) -> ~1e-5 rel accuracy.
// BM=128, BN=128, K=256 (chunks 0-3: A/Wl, 4-7: H/Wr, BK=32).
// 256 threads = 8 warps (4x2), warp tile 32x64.
__device__ __forceinline__ void mma_bf16(float* c, const unsigned* a, const unsigned* b) {
    asm volatile(
        "mma.sync.aligned.m16n8k16.row.col.f32.bf16.bf16.f32 "
        "{%0,%1,%2,%3}, {%4,%5,%6,%7}, {%8,%9}, {%0,%1,%2,%3};\n"
        : "+f"(c[0]), "+f"(c[1]), "+f"(c[2]), "+f"(c[3])
        : "r"(a[0]), "r"(a[1]), "r"(a[2]), "r"(a[3]), "r"(b[0]), "r"(b[1]));
}

__global__ void __launch_bounds__(256)
k_gemm_tc(const float* __restrict__ A, const float* __restrict__ H,
          const float* __restrict__ Wl, const float* __restrict__ Wr,
          const float* __restrict__ bias, float* __restrict__ out, int M)
{
    __shared__ __nv_bfloat16 sAhi[128][36], sAlo[128][36];
    __shared__ __nv_bfloat16 sWhi[128][36], sWlo[128][36];

    const int tid  = threadIdx.x;
    const int lane = tid & 31, warp = tid >> 5;
    const int wm = warp & 3, wn = warp >> 2;   // 4 x 2 warp grid
    const int g  = lane >> 2, t = lane & 3;
    const int row0 = blockIdx.x * 128;

    float acc[2][8][4];
    #pragma unroll
    for (int a = 0; a < 2; a++)
        #pragma unroll
        for (int b = 0; b < 8; b++)
            #pragma unroll
            for (int c = 0; c < 4; c++) acc[a][b][c] = 0.f;

    for (int kc = 0; kc < 8; kc++) {
        const float* src  = (kc < 4) ? A  : H;
        const float* Wsrc = (kc < 4) ? Wl : Wr;
        const int koff = (kc & 3) * 32;

        // A tile: 128 rows x 32 k, fp32 -> bf16 hi/lo
        #pragma unroll
        for (int j = 0; j < 4; j++) {
            int i = tid + j * 256;          // 0..1023 float4 slots
            int r = i >> 3;                 // 0..127
            int k = (i & 7) * 4;
            float4 v = make_float4(0.f, 0.f, 0.f, 0.f);
            int gr = row0 + r;
            if (gr < M) v = *(const float4*)(src + (size_t)gr * 128 + koff + k);
            float vv[4] = {v.x, v.y, v.z, v.w};
            #pragma unroll
            for (int q = 0; q < 4; q++) {
                __nv_bfloat16 hh = __float2bfloat16_rn(vv[q]);
                sAhi[r][k + q] = hh;
                sAlo[r][k + q] = __float2bfloat16_rn(vv[q] - __bfloat162float(hh));
            }
        }
        // W tile: 32 k x 128 n, transposed into sW[n][k]
        #pragma unroll
        for (int j = 0; j < 4; j++) {
            int i = tid + j * 256;
            int r = i >> 5;                 // k 0..31
            int c = (i & 31) * 4;           // n
            float4 v = *(const float4*)(Wsrc + (size_t)(koff + r) * 128 + c);
            float vv[4] = {v.x, v.y, v.z, v.w};
            #pragma unroll
            for (int q = 0; q < 4; q++) {
                __nv_bfloat16 hh = __float2bfloat16_rn(vv[q]);
                sWhi[c + q][r] = hh;
                sWlo[c + q][r] = __float2bfloat16_rn(vv[q] - __bfloat162float(hh));
            }
        }
        __syncthreads();

        #pragma unroll
        for (int k0 = 0; k0 < 32; k0 += 16) {
            unsigned ahi[2][4], alo[2][4];
            #pragma unroll
            for (int mt = 0; mt < 2; mt++) {
                int rm = wm * 32 + mt * 16;
                ahi[mt][0] = *(const unsigned*)&sAhi[rm + g    ][k0 + 2 * t];
                ahi[mt][1] = *(const unsigned*)&sAhi[rm + 8 + g][k0 + 2 * t];
                ahi[mt][2] = *(const unsigned*)&sAhi[rm + g    ][k0 + 2 * t + 8];
                ahi[mt][3] = *(const unsigned*)&sAhi[rm + 8 + g][k0 + 2 * t + 8];
                alo[mt][0] = *(const unsigned*)&sAlo[rm + g    ][k0 + 2 * t];
                alo[mt][1] = *(const unsigned*)&sAlo[rm + 8 + g][k0 + 2 * t];
                alo[mt][2] = *(const unsigned*)&sAlo[rm + g    ][k0 + 2 * t + 8];
                alo[mt][3] = *(const unsigned*)&sAlo[rm + 8 + g][k0 + 2 * t + 8];
            }
            #pragma unroll
            for (int nt = 0; nt < 8; nt++) {
                int cn = wn * 64 + nt * 8 + g;
                unsigned bhi[2], blo[2];
                bhi[0] = *(const unsigned*)&sWhi[cn][k0 + 2 * t];
                bhi[1] = *(const unsigned*)&sWhi[cn][k0 + 2 * t + 8];
                blo[0] = *(const unsigned*)&sWlo[cn][k0 + 2 * t];
                blo[1] = *(const unsigned*)&sWlo[cn][k0 + 2 * t + 8];
                #pragma unroll
                for (int mt = 0; mt < 2; mt++) {
                    mma_bf16(acc[mt][nt], ahi[mt], bhi);
                    mma_bf16(acc[mt][nt], ahi[mt], blo);
                    mma_bf16(acc[mt][nt], alo[mt], bhi);
                }
            }
        }
        __syncthreads();
    }

    // epilogue: + bias, relu, store
    #pragma unroll
    for (int mt = 0; mt < 2; mt++) {
        int r0 = row0 + wm * 32 + mt * 16 + g;
        #pragma unroll
        for (int nt = 0; nt < 8; nt++) {
            int c = wn * 64 + nt * 8 + 2 * t;
            float b0 = __ldg(bias + c), b1 = __ldg(bias + c + 1);
            if (r0 < M) {
                float2 o;
                o.x = fmaxf(acc[mt][nt][0] + b0, 0.f);
                o.y = fmaxf(acc[mt][nt][1] + b1, 0.f);
                *(float2*)(out + (size_t)r0 * 128 + c) = o;
            }
            if (r0 + 8 < M) {
                float2 o;
                o.x = fmaxf(acc[mt][nt][2] + b0, 0.f);
                o.y = fmaxf(acc[mt][nt][3] + b1, 0.f);
                *(float2*)(out + (size_t)(r0 + 8) * 128 + c) = o;
            }
        }
    }
}

// ---------------- per-graph boundaries (batch is sorted) --------------------
__global__ void k_bounds(const void* __restrict__ batch, int n) {
    int g = blockIdx.x * blockDim.x + threadIdx.x;
    if (g > NG) return;
    int lo = 0, hi = n;
    while (lo < hi) {
        int mid = (lo + hi) >> 1;
        if (idx_at(batch, mid) < (long long)g) lo = mid + 1; else hi = mid;
    }
    g_gstart[g] = lo;
}

// ---------------- meanmax readout: one block per graph ----------------------
__global__ void k_readout(const float* __restrict__ h, float* __restrict__ out) {
    int g = blockIdx.x;
    int c = threadIdx.x;                 // 0..127
    int s = g_gstart[g], e = g_gstart[g + 1];
    float sum = 0.f, mx = 0.f;           // post-relu values >= 0; empty -> 0
    for (int n = s; n < e; n++) {
        float v = __ldg(h + (size_t)n * DIM + c);
        sum += v;
        mx = fmaxf(mx, v);
    }
    out[g * (2 * DIM) + c]       = sum / fmaxf((float)(e - s), 1.f);
    out[g * (2 * DIM) + DIM + c] = mx;
}

// ---------------- launcher ---------------------------------------------------
extern "C" void kernel_launch(void* const* d_in, const int* in_sizes, int n_in,
                              void* d_out, int out_size)
{
    const float* x     = (const float*)d_in[0];
    const void*  ei    = d_in[1];
    const void*  batch = d_in[2];
    const float* Wl0 = (const float*)d_in[3];
    const float* bl0 = (const float*)d_in[4];
    const float* Wr0 = (const float*)d_in[5];
    const float* Wl1 = (const float*)d_in[6];
    const float* bl1 = (const float*)d_in[7];
    const float* Wr1 = (const float*)d_in[8];
    const float* Wl2 = (const float*)d_in[9];
    const float* bl2 = (const float*)d_in[10];
    const float* Wr2 = (const float*)d_in[11];
    float* out = (float*)d_out;

    const int N = in_sizes[0] / DIM;     // 50000
    const int E = in_sizes[1] / 2;       // 800000

    float *agg, *bufA, *bufB;
    cudaGetSymbolAddress((void**)&agg,  g_agg);
    cudaGetSymbolAddress((void**)&bufA, g_bufA);
    cudaGetSymbolAddress((void**)&bufB, g_bufB);

    const int nb = (N + 255) / 256;      // scan blocks (196)

    k_init  <<<(NN + 255) / 256, 256>>>();
    k_detect<<<(E + 255) / 256, 256>>>((const int*)ei, 2 * E);
    k_count <<<(E + 255) / 256, 256>>>(ei, E);
    k_bsum  <<<nb, 256>>>(N);
    k_bscan <<<1, 256>>>(nb, N);
    k_rowptr<<<nb, 256>>>(N);
    k_fill  <<<(E + 255) / 256, 256>>>(ei, E);

    const int aggGrid  = (N * 32 + 255) / 256;    // one warp per node
    const int gemmGrid = (N + 127) / 128;

    // layer 0: h = x
    k_agg    <<<aggGrid, 256>>>(x, N);
    k_gemm_tc<<<gemmGrid, 256>>>(agg, x, Wl0, Wr0, bl0, bufA, N);
    // layer 1
    k_agg    <<<aggGrid, 256>>>(bufA, N);
    k_gemm_tc<<<gemmGrid, 256>>>(agg, bufA, Wl1, Wr1, bl1, bufB, N);
    // layer 2
    k_agg    <<<aggGrid, 256>>>(bufB, N);
    k_gemm_tc<<<gemmGrid, 256>>>(agg, bufB, Wl2, Wr2, bl2, bufA, N);

    k_bounds <<<1, 512>>>(batch, N);
    k_readout<<<NG, DIM>>>(bufA, out);
}

// round 3
// speedup vs baseline: 1.4464x; 1.2191x over previous
#include <cuda_runtime.h>
#include <cuda_bf16.h>
#include <stdint.h>

#define NN 50000
#define NG 256
#define DIM 128
#define NE 800000

typedef __nv_bfloat16 bf16;

// ---------------- scratch (static __device__ => no runtime allocation) ------
__device__ float g_bufA[NN * DIM];
__device__ float g_bufB[NN * DIM];
__device__ bf16  g_aggHi[NN * DIM], g_aggLo[NN * DIM];
__device__ bf16  g_h0Hi [NN * DIM], g_h0Lo [NN * DIM];
__device__ bf16  g_h1Hi [NN * DIM], g_h1Lo [NN * DIM];
__device__ bf16  g_h2Hi [NN * DIM], g_h2Lo [NN * DIM];
__device__ bf16  g_wtHi[6 * DIM * DIM], g_wtLo[6 * DIM * DIM];
__device__ int   g_rowptr[NN + 1];
__device__ int   g_cnt[NN];
__device__ int   g_col[NE];
__device__ int   g_gstart[NG + 1];
__device__ int   g_is64;
__device__ int   g_bsum[256];
__device__ int   g_boff[256];

// ---------------- dtype-agnostic index access -------------------------------
__device__ __forceinline__ long long idx_at(const void* p, long long i) {
    if (g_is64) return ((const long long*)p)[i];
    return (long long)((const int*)p)[i];
}

__device__ __forceinline__ void split2(float a, float b, unsigned& hi, unsigned& lo) {
    bf16 ha = __float2bfloat16_rn(a), hb = __float2bfloat16_rn(b);
    bf16 la = __float2bfloat16_rn(a - __bfloat162float(ha));
    bf16 lb = __float2bfloat16_rn(b - __bfloat162float(hb));
    __nv_bfloat162 h2 = __nv_bfloat162(ha, hb), l2 = __nv_bfloat162(la, lb);
    hi = *(unsigned*)&h2; lo = *(unsigned*)&l2;
}

// ---------------- init: zero counters, assume int64 until disproven ---------
__global__ void k_init() {
    int i = blockIdx.x * blockDim.x + threadIdx.x;
    if (i < NN) g_cnt[i] = 0;
    if (i == 0) g_is64 = 1;
}

// Sample first 4096 32-bit words. If edges are int64 (nonneg < 2^31) the odd
// words are all zero; if int32 they are ~2048 random node ids (P(all 0) ~= 0).
__global__ void k_detect(const int* __restrict__ ei32, int e2) {
    int idx = 2 * threadIdx.x + 1;
    for (int k = 0; k < 8; k++, idx += 512)
        if (idx < e2 && idx < 4096 && ei32[idx] != 0) g_is64 = 0;
}

// ---------------- CSR build --------------------------------------------------
__global__ void k_count(const void* __restrict__ ei, int E) {
    int e = blockIdx.x * blockDim.x + threadIdx.x;
    if (e >= E) return;
    int d = (int)idx_at(ei, (long long)E + e);
    atomicAdd(&g_cnt[d], 1);
}

__device__ __forceinline__ int blk_excl_scan(int v, int* warpsum) {
    int tid = threadIdx.x, lane = tid & 31, w = tid >> 5;
    int x = v;
    #pragma unroll
    for (int o = 1; o < 32; o <<= 1) {
        int y = __shfl_up_sync(0xFFFFFFFFu, x, o);
        if (lane >= o) x += y;
    }
    if (lane == 31) warpsum[w] = x;
    __syncthreads();
    if (w == 0 && lane < 8) {
        int s = warpsum[lane];
        #pragma unroll
        for (int o = 1; o < 8; o <<= 1) {
            int y = __shfl_up_sync(0xFFu, s, o);
            if (lane >= o) s += y;
        }
        warpsum[lane] = s;
    }
    __syncthreads();
    return x - v + (w > 0 ? warpsum[w - 1] : 0);
}

__global__ void k_bsum(int n) {
    __shared__ int warpsum[8];
    int i = blockIdx.x * 256 + threadIdx.x;
    int v = (i < n) ? g_cnt[i] : 0;
    int lane = threadIdx.x & 31, w = threadIdx.x >> 5;
    #pragma unroll
    for (int o = 16; o > 0; o >>= 1) v += __shfl_down_sync(0xFFFFFFFFu, v, o);
    if (lane == 0) warpsum[w] = v;
    __syncthreads();
    if (threadIdx.x == 0) {
        int s = 0;
        #pragma unroll
        for (int k = 0; k < 8; k++) s += warpsum[k];
        g_bsum[blockIdx.x] = s;
    }
}

__global__ void k_bscan(int nb, int n) {
    __shared__ int warpsum[8];
    int t = threadIdx.x;
    int v = (t < nb) ? g_bsum[t] : 0;
    int excl = blk_excl_scan(v, warpsum);
    if (t < nb) g_boff[t] = excl;
    if (t == nb - 1) g_rowptr[n] = excl + v;
}

__global__ void k_rowptr(int n) {
    __shared__ int warpsum[8];
    int i = blockIdx.x * 256 + threadIdx.x;
    int v = (i < n) ? g_cnt[i] : 0;
    int excl = blk_excl_scan(v, warpsum);
    if (i < n) { g_rowptr[i] = g_boff[blockIdx.x] + excl; g_cnt[i] = 0; }
}

__global__ void k_fill(const void* __restrict__ ei, int E) {
    int e = blockIdx.x * blockDim.x + threadIdx.x;
    if (e >= E) return;
    int s = (int)idx_at(ei, e);
    int d = (int)idx_at(ei, (long long)E + e);
    int pos = g_rowptr[d] + atomicAdd(&g_cnt[d], 1);
    g_col[pos] = s;
}

// ---------------- prep: split x, transpose+split weights --------------------
__global__ void k_prepx(const float* __restrict__ x, int n4) {
    int i = blockIdx.x * blockDim.x + threadIdx.x;
    if (i >= n4) return;
    float4 v = *(const float4*)(x + (size_t)i * 4);
    uint2 hi, lo;
    split2(v.x, v.y, hi.x, lo.x);
    split2(v.z, v.w, hi.y, lo.y);
    *(uint2*)(g_h0Hi + (size_t)i * 4) = hi;
    *(uint2*)(g_h0Lo + (size_t)i * 4) = lo;
}

// one matrix per blockIdx.y; Wt[m][n][k] = W[m][k][n]
__global__ void k_prepw(const float* __restrict__ W0, const float* __restrict__ W1,
                        const float* __restrict__ W2, const float* __restrict__ W3,
                        const float* __restrict__ W4, const float* __restrict__ W5) {
    const float* Ws[6] = {W0, W1, W2, W3, W4, W5};
    int m = blockIdx.y;
    int i = blockIdx.x * blockDim.x + threadIdx.x;   // 0..16383
    if (i >= DIM * DIM) return;
    int n = i >> 7, k = i & 127;
    float v = Ws[m][k * DIM + n];
    bf16 h = __float2bfloat16_rn(v);
    bf16 l = __float2bfloat16_rn(v - __bfloat162float(h));
    g_wtHi[m * DIM * DIM + i] = h;
    g_wtLo[m * DIM * DIM + i] = l;
}

// ---------------- mean aggregation: one warp per node, emits bf16 hi/lo -----
__global__ void k_agg(const float* __restrict__ h, int N) {
    int warp = (blockIdx.x * blockDim.x + threadIdx.x) >> 5;
    int lane = threadIdx.x & 31;
    if (warp >= N) return;
    int beg = g_rowptr[warp], end = g_rowptr[warp + 1];
    float4 acc = make_float4(0.f, 0.f, 0.f, 0.f);
    int i = beg;
    for (; i + 1 < end; i += 2) {
        int s0 = __ldg(&g_col[i]), s1 = __ldg(&g_col[i + 1]);
        float4 v0 = *(const float4*)(h + (size_t)s0 * DIM + lane * 4);
        float4 v1 = *(const float4*)(h + (size_t)s1 * DIM + lane * 4);
        acc.x += v0.x + v1.x; acc.y += v0.y + v1.y;
        acc.z += v0.z + v1.z; acc.w += v0.w + v1.w;
    }
    if (i < end) {
        int s0 = __ldg(&g_col[i]);
        float4 v0 = *(const float4*)(h + (size_t)s0 * DIM + lane * 4);
        acc.x += v0.x; acc.y += v0.y; acc.z += v0.z; acc.w += v0.w;
    }
    int deg = end - beg;
    float inv = 1.0f / (float)(deg > 0 ? deg : 1);
    uint2 hi, lo;
    split2(acc.x * inv, acc.y * inv, hi.x, lo.x);
    split2(acc.z * inv, acc.w * inv, hi.y, lo.y);
    size_t off = (size_t)warp * DIM + lane * 4;
    *(uint2*)(g_aggHi + off) = hi;
    *(uint2*)(g_aggLo + off) = lo;
}

// ---------------- tensor-core fused dual GEMM --------------------------------
// out = relu(A@Wl + H@Wr + bias); operands pre-split bf16 hi/lo in global.
// 3-product accumulation: hi*hi + hi*lo + lo*hi  (~1e-5 accuracy).
// BM=128, BN=128; 8 chunks of BK=32 (0-3: A/Wl, 4-7: H/Wr). 8 warps (4x2).
__device__ __forceinline__ void mma_bf16(float* c, const unsigned* a, const unsigned* b) {
    asm volatile(
        "mma.sync.aligned.m16n8k16.row.col.f32.bf16.bf16.f32 "
        "{%0,%1,%2,%3}, {%4,%5,%6,%7}, {%8,%9}, {%0,%1,%2,%3};\n"
        : "+f"(c[0]), "+f"(c[1]), "+f"(c[2]), "+f"(c[3])
        : "r"(a[0]), "r"(a[1]), "r"(a[2]), "r"(a[3]), "r"(b[0]), "r"(b[1]));
}

__global__ void __launch_bounds__(256)
k_gemm_tc(const bf16* __restrict__ Ahi, const bf16* __restrict__ Alo,
          const bf16* __restrict__ Hhi, const bf16* __restrict__ Hlo,
          const bf16* __restrict__ WtHi, const bf16* __restrict__ WtLo,
          const float* __restrict__ bias, float* __restrict__ out,
          bf16* __restrict__ outHi, bf16* __restrict__ outLo, int M)
{
    __shared__ __align__(16) bf16 sAhi[128][36], sAlo[128][36];
    __shared__ __align__(16) bf16 sWhi[128][36], sWlo[128][36];

    const int tid  = threadIdx.x;
    const int lane = tid & 31, warp = tid >> 5;
    const int wm = warp & 3, wn = warp >> 2;   // 4 x 2 warp grid
    const int g  = lane >> 2, t = lane & 3;
    const int row0 = blockIdx.x * 128;

    float acc[2][8][4];
    #pragma unroll
    for (int a = 0; a < 2; a++)
        #pragma unroll
        for (int b = 0; b < 8; b++)
            #pragma unroll
            for (int c = 0; c < 4; c++) acc[a][b][c] = 0.f;

    for (int kc = 0; kc < 8; kc++) {
        const bf16* srcHi = (kc < 4) ? Ahi : Hhi;
        const bf16* srcLo = (kc < 4) ? Alo : Hlo;
        const bf16* wHi   = WtHi + ((kc < 4) ? 0 : DIM * DIM);
        const bf16* wLo   = WtLo + ((kc < 4) ? 0 : DIM * DIM);
        const int koff = (kc & 3) * 32;

        // A tile: 128 rows x 32 k, direct bf16 copy (vectorized)
        #pragma unroll
        for (int j = 0; j < 2; j++) {
            int i = tid + j * 256;            // 0..511 uint4 slots
            int r = i >> 2, k8 = (i & 3) * 8;
            int gr = row0 + r;
            uint4 vh = make_uint4(0u,0u,0u,0u), vl = vh;
            if (gr < M) {
                size_t off = (size_t)gr * DIM + koff + k8;
                vh = *(const uint4*)(srcHi + off);
                vl = *(const uint4*)(srcLo + off);
            }
            *(uint2*)&sAhi[r][k8]     = make_uint2(vh.x, vh.y);
            *(uint2*)&sAhi[r][k8 + 4] = make_uint2(vh.z, vh.w);
            *(uint2*)&sAlo[r][k8]     = make_uint2(vl.x, vl.y);
            *(uint2*)&sAlo[r][k8 + 4] = make_uint2(vl.z, vl.w);
        }
        // W tile: [n][k] layout in global already; copy 128 n x 32 k
        #pragma unroll
        for (int j = 0; j < 2; j++) {
            int i = tid + j * 256;
            int n = i >> 2, k8 = (i & 3) * 8;
            size_t off = (size_t)n * DIM + koff + k8;
            uint4 vh = *(const uint4*)(wHi + off);
            uint4 vl = *(const uint4*)(wLo + off);
            *(uint2*)&sWhi[n][k8]     = make_uint2(vh.x, vh.y);
            *(uint2*)&sWhi[n][k8 + 4] = make_uint2(vh.z, vh.w);
            *(uint2*)&sWlo[n][k8]     = make_uint2(vl.x, vl.y);
            *(uint2*)&sWlo[n][k8 + 4] = make_uint2(vl.z, vl.w);
        }
        __syncthreads();

        #pragma unroll
        for (int k0 = 0; k0 < 32; k0 += 16) {
            unsigned ahi[2][4], alo[2][4];
            #pragma unroll
            for (int mt = 0; mt < 2; mt++) {
                int rm = wm * 32 + mt * 16;
                ahi[mt][0] = *(const unsigned*)&sAhi[rm + g    ][k0 + 2 * t];
                ahi[mt][1] = *(const unsigned*)&sAhi[rm + 8 + g][k0 + 2 * t];
                ahi[mt][2] = *(const unsigned*)&sAhi[rm + g    ][k0 + 2 * t + 8];
                ahi[mt][3] = *(const unsigned*)&sAhi[rm + 8 + g][k0 + 2 * t + 8];
                alo[mt][0] = *(const unsigned*)&sAlo[rm + g    ][k0 + 2 * t];
                alo[mt][1] = *(const unsigned*)&sAlo[rm + 8 + g][k0 + 2 * t];
                alo[mt][2] = *(const unsigned*)&sAlo[rm + g    ][k0 + 2 * t + 8];
                alo[mt][3] = *(const unsigned*)&sAlo[rm + 8 + g][k0 + 2 * t + 8];
            }
            #pragma unroll
            for (int nt = 0; nt < 8; nt++) {
                int cn = wn * 64 + nt * 8 + g;
                unsigned bhi[2], blo[2];
                bhi[0] = *(const unsigned*)&sWhi[cn][k0 + 2 * t];
                bhi[1] = *(const unsigned*)&sWhi[cn][k0 + 2 * t + 8];
                blo[0] = *(const unsigned*)&sWlo[cn][k0 + 2 * t];
                blo[1] = *(const unsigned*)&sWlo[cn][k0 + 2 * t + 8];
                #pragma unroll
                for (int mt = 0; mt < 2; mt++) {
                    mma_bf16(acc[mt][nt], ahi[mt], bhi);
                    mma_bf16(acc[mt][nt], ahi[mt], blo);
                    mma_bf16(acc[mt][nt], alo[mt], bhi);
                }
            }
        }
        __syncthreads();
    }

    // epilogue: + bias, relu, store fp32 + bf16 hi/lo
    #pragma unroll
    for (int mt = 0; mt < 2; mt++) {
        int r0 = row0 + wm * 32 + mt * 16 + g;
        #pragma unroll
        for (int nt = 0; nt < 8; nt++) {
            int c = wn * 64 + nt * 8 + 2 * t;
            float b0 = __ldg(bias + c), b1 = __ldg(bias + c + 1);
            #pragma unroll
            for (int half = 0; half < 2; half++) {
                int rr = r0 + half * 8;
                if (rr < M) {
                    float ox = fmaxf(acc[mt][nt][2 * half]     + b0, 0.f);
                    float oy = fmaxf(acc[mt][nt][2 * half + 1] + b1, 0.f);
                    size_t off = (size_t)rr * DIM + c;
                    *(float2*)(out + off) = make_float2(ox, oy);
                    unsigned hi, lo;
                    split2(ox, oy, hi, lo);
                    *(unsigned*)(outHi + off) = hi;
                    *(unsigned*)(outLo + off) = lo;
                }
            }
        }
    }
}

// ---------------- per-graph boundaries (batch is sorted) --------------------
__global__ void k_bounds(const void* __restrict__ batch, int n) {
    int g = blockIdx.x * blockDim.x + threadIdx.x;
    if (g > NG) return;
    int lo = 0, hi = n;
    while (lo < hi) {
        int mid = (lo + hi) >> 1;
        if (idx_at(batch, mid) < (long long)g) lo = mid + 1; else hi = mid;
    }
    g_gstart[g] = lo;
}

// ---------------- meanmax readout: one block per graph ----------------------
__global__ void k_readout(const float* __restrict__ h, float* __restrict__ out) {
    int g = blockIdx.x;
    int c = threadIdx.x;                 // 0..127
    int s = g_gstart[g], e = g_gstart[g + 1];
    float sum = 0.f, mx = 0.f;           // post-relu values >= 0; empty -> 0
    for (int n = s; n < e; n++) {
        float v = __ldg(h + (size_t)n * DIM + c);
        sum += v;
        mx = fmaxf(mx, v);
    }
    out[g * (2 * DIM) + c]       = sum / fmaxf((float)(e - s), 1.f);
    out[g * (2 * DIM) + DIM + c] = mx;
}

// ---------------- launcher ---------------------------------------------------
extern "C" void kernel_launch(void* const* d_in, const int* in_sizes, int n_in,
                              void* d_out, int out_size)
{
    const float* x     = (const float*)d_in[0];
    const void*  ei    = d_in[1];
    const void*  batch = d_in[2];
    const float* Wl0 = (const float*)d_in[3];
    const float* bl0 = (const float*)d_in[4];
    const float* Wr0 = (const float*)d_in[5];
    const float* Wl1 = (const float*)d_in[6];
    const float* bl1 = (const float*)d_in[7];
    const float* Wr1 = (const float*)d_in[8];
    const float* Wl2 = (const float*)d_in[9];
    const float* bl2 = (const float*)d_in[10];
    const float* Wr2 = (const float*)d_in[11];
    float* out = (float*)d_out;

    const int N = in_sizes[0] / DIM;     // 50000
    const int E = in_sizes[1] / 2;       // 800000

    float *bufA, *bufB;
    bf16 *aggHi, *aggLo, *h0Hi, *h0Lo, *h1Hi, *h1Lo, *h2Hi, *h2Lo, *wtHi, *wtLo;
    cudaGetSymbolAddress((void**)&bufA, g_bufA);
    cudaGetSymbolAddress((void**)&bufB, g_bufB);
    cudaGetSymbolAddress((void**)&aggHi, g_aggHi);
    cudaGetSymbolAddress((void**)&aggLo, g_aggLo);
    cudaGetSymbolAddress((void**)&h0Hi, g_h0Hi);
    cudaGetSymbolAddress((void**)&h0Lo, g_h0Lo);
    cudaGetSymbolAddress((void**)&h1Hi, g_h1Hi);
    cudaGetSymbolAddress((void**)&h1Lo, g_h1Lo);
    cudaGetSymbolAddress((void**)&h2Hi, g_h2Hi);
    cudaGetSymbolAddress((void**)&h2Lo, g_h2Lo);
    cudaGetSymbolAddress((void**)&wtHi, g_wtHi);
    cudaGetSymbolAddress((void**)&wtLo, g_wtLo);

    const int nb = (N + 255) / 256;

    k_init  <<<(NN + 255) / 256, 256>>>();
    k_detect<<<1, 256>>>((const int*)ei, 2 * E);
    k_count <<<(E + 255) / 256, 256>>>(ei, E);
    k_bsum  <<<nb, 256>>>(N);
    k_bscan <<<1, 256>>>(nb, N);
    k_rowptr<<<nb, 256>>>(N);
    k_fill  <<<(E + 255) / 256, 256>>>(ei, E);

    k_prepx <<<(N * 32 + 255) / 256, 256>>>(x, N * 32);
    {
        dim3 gw((DIM * DIM + 255) / 256, 6);
        k_prepw<<<gw, 256>>>(Wl0, Wr0, Wl1, Wr1, Wl2, Wr2);
    }

    const int aggGrid  = (N * 32 + 255) / 256;    // one warp per node
    const int gemmGrid = (N + 127) / 128;

    // layer 0: A = agg(x), H = x
    k_agg    <<<aggGrid, 256>>>(x, N);
    k_gemm_tc<<<gemmGrid, 256>>>(aggHi, aggLo, h0Hi, h0Lo,
                                 wtHi + 0 * DIM * DIM, wtLo + 0 * DIM * DIM,
                                 bl0, bufA, h1Hi, h1Lo, N);
    // layer 1
    k_agg    <<<aggGrid, 256>>>(bufA, N);
    k_gemm_tc<<<gemmGrid, 256>>>(aggHi, aggLo, h1Hi, h1Lo,
                                 wtHi + 2 * DIM * DIM, wtLo + 2 * DIM * DIM,
                                 bl1, bufB, h2Hi, h2Lo, N);
    // layer 2
    k_agg    <<<aggGrid, 256>>>(bufB, N);
    k_gemm_tc<<<gemmGrid, 256>>>(aggHi, aggLo, h2Hi, h2Lo,
                                 wtHi + 4 * DIM * DIM, wtLo + 4 * DIM * DIM,
                                 bl2, bufA, h1Hi, h1Lo, N);

    k_bounds <<<1, 512>>>(batch, N);
    k_readout<<<NG, DIM>>>(bufA, out);
}

// round 4
// speedup vs baseline: 1.5025x; 1.0388x over previous
#include <cuda_runtime.h>
#include <cuda_bf16.h>
#include <cuda_fp16.h>
#include <stdint.h>

#define NN 50000
#define NG 256
#define DIM 128
#define NE 800000

typedef __nv_bfloat16 bf16;

// ---------------- scratch (static __device__ => no runtime allocation) ------
__device__ __half g_xf  [NN * DIM];               // fp16 copy of x (gather src)
__device__ __half g_hfA [NN * DIM];               // fp16 layer outputs (ping)
__device__ __half g_hfB [NN * DIM];               // fp16 layer outputs (pong)
__device__ bf16  g_aggHi[NN * DIM], g_aggLo[NN * DIM];
__device__ bf16  g_h0Hi [NN * DIM], g_h0Lo [NN * DIM];
__device__ bf16  g_h1Hi [NN * DIM], g_h1Lo [NN * DIM];
__device__ bf16  g_h2Hi [NN * DIM], g_h2Lo [NN * DIM];
__device__ bf16  g_wtHi[6 * DIM * DIM], g_wtLo[6 * DIM * DIM];
__device__ int   g_rowptr[NN + 1];
__device__ int   g_cnt[NN];
__device__ int   g_col[NE];
__device__ int   g_gstart[NG + 1];
__device__ int   g_is64;
__device__ int   g_bsum[256];
__device__ int   g_boff[256];

// ---------------- dtype-agnostic index access -------------------------------
__device__ __forceinline__ long long idx_at(const void* p, long long i) {
    if (g_is64) return ((const long long*)p)[i];
    return (long long)((const int*)p)[i];
}

__device__ __forceinline__ void split2(float a, float b, unsigned& hi, unsigned& lo) {
    bf16 ha = __float2bfloat16_rn(a), hb = __float2bfloat16_rn(b);
    bf16 la = __float2bfloat16_rn(a - __bfloat162float(ha));
    bf16 lb = __float2bfloat16_rn(b - __bfloat162float(hb));
    __nv_bfloat162 h2 = __nv_bfloat162(ha, hb), l2 = __nv_bfloat162(la, lb);
    hi = *(unsigned*)&h2; lo = *(unsigned*)&l2;
}

// ---------------- init: zero counters, assume int64 until disproven ---------
__global__ void k_init() {
    int i = blockIdx.x * blockDim.x + threadIdx.x;
    if (i < NN) g_cnt[i] = 0;
    if (i == 0) g_is64 = 1;
}

// Sample first 4096 32-bit words. If edges are int64 (nonneg < 2^31) the odd
// words are all zero; if int32 they are ~2048 random node ids (P(all 0) ~= 0).
__global__ void k_detect(const int* __restrict__ ei32, int e2) {
    int idx = 2 * threadIdx.x + 1;
    for (int k = 0; k < 8; k++, idx += 512)
        if (idx < e2 && idx < 4096 && ei32[idx] != 0) g_is64 = 0;
}

// ---------------- CSR build --------------------------------------------------
__global__ void k_count(const void* __restrict__ ei, int E) {
    int e = blockIdx.x * blockDim.x + threadIdx.x;
    if (e >= E) return;
    int d = (int)idx_at(ei, (long long)E + e);
    atomicAdd(&g_cnt[d], 1);
}

__device__ __forceinline__ int blk_excl_scan(int v, int* warpsum) {
    int tid = threadIdx.x, lane = tid & 31, w = tid >> 5;
    int x = v;
    #pragma unroll
    for (int o = 1; o < 32; o <<= 1) {
        int y = __shfl_up_sync(0xFFFFFFFFu, x, o);
        if (lane >= o) x += y;
    }
    if (lane == 31) warpsum[w] = x;
    __syncthreads();
    if (w == 0 && lane < 8) {
        int s = warpsum[lane];
        #pragma unroll
        for (int o = 1; o < 8; o <<= 1) {
            int y = __shfl_up_sync(0xFFu, s, o);
            if (lane >= o) s += y;
        }
        warpsum[lane] = s;
    }
    __syncthreads();
    return x - v + (w > 0 ? warpsum[w - 1] : 0);
}

__global__ void k_bsum(int n) {
    __shared__ int warpsum[8];
    int i = blockIdx.x * 256 + threadIdx.x;
    int v = (i < n) ? g_cnt[i] : 0;
    int lane = threadIdx.x & 31, w = threadIdx.x >> 5;
    #pragma unroll
    for (int o = 16; o > 0; o >>= 1) v += __shfl_down_sync(0xFFFFFFFFu, v, o);
    if (lane == 0) warpsum[w] = v;
    __syncthreads();
    if (threadIdx.x == 0) {
        int s = 0;
        #pragma unroll
        for (int k = 0; k < 8; k++) s += warpsum[k];
        g_bsum[blockIdx.x] = s;
    }
}

__global__ void k_bscan(int nb, int n) {
    __shared__ int warpsum[8];
    int t = threadIdx.x;
    int v = (t < nb) ? g_bsum[t] : 0;
    int excl = blk_excl_scan(v, warpsum);
    if (t < nb) g_boff[t] = excl;
    if (t == nb - 1) g_rowptr[n] = excl + v;
}

__global__ void k_rowptr(int n) {
    __shared__ int warpsum[8];
    int i = blockIdx.x * 256 + threadIdx.x;
    int v = (i < n) ? g_cnt[i] : 0;
    int excl = blk_excl_scan(v, warpsum);
    if (i < n) { g_rowptr[i] = g_boff[blockIdx.x] + excl; g_cnt[i] = 0; }
}

__global__ void k_fill(const void* __restrict__ ei, int E) {
    int e = blockIdx.x * blockDim.x + threadIdx.x;
    if (e >= E) return;
    int s = (int)idx_at(ei, e);
    int d = (int)idx_at(ei, (long long)E + e);
    int pos = g_rowptr[d] + atomicAdd(&g_cnt[d], 1);
    g_col[pos] = s;
}

// ---------------- prep: split x (bf16 hi/lo + fp16), transpose+split weights -
__global__ void k_prepx(const float* __restrict__ x, int n4) {
    int i = blockIdx.x * blockDim.x + threadIdx.x;
    if (i >= n4) return;
    float4 v = *(const float4*)(x + (size_t)i * 4);
    uint2 hi, lo;
    split2(v.x, v.y, hi.x, lo.x);
    split2(v.z, v.w, hi.y, lo.y);
    *(uint2*)(g_h0Hi + (size_t)i * 4) = hi;
    *(uint2*)(g_h0Lo + (size_t)i * 4) = lo;
    __half2 f0 = __floats2half2_rn(v.x, v.y);
    __half2 f1 = __floats2half2_rn(v.z, v.w);
    *(__half2*)(g_xf + (size_t)i * 4)     = f0;
    *(__half2*)(g_xf + (size_t)i * 4 + 2) = f1;
}

// one matrix per blockIdx.y; Wt[m][n][k] = W[m][k][n]
__global__ void k_prepw(const float* __restrict__ W0, const float* __restrict__ W1,
                        const float* __restrict__ W2, const float* __restrict__ W3,
                        const float* __restrict__ W4, const float* __restrict__ W5) {
    const float* Ws[6] = {W0, W1, W2, W3, W4, W5};
    int m = blockIdx.y;
    int i = blockIdx.x * blockDim.x + threadIdx.x;   // 0..16383
    if (i >= DIM * DIM) return;
    int n = i >> 7, k = i & 127;
    float v = Ws[m][k * DIM + n];
    bf16 h = __float2bfloat16_rn(v);
    bf16 l = __float2bfloat16_rn(v - __bfloat162float(h));
    g_wtHi[m * DIM * DIM + i] = h;
    g_wtLo[m * DIM * DIM + i] = l;
}

// ---------------- mean aggregation: one warp per node, fp16 gather ----------
// Each lane covers 4 columns (8 bytes) of the 128-wide fp16 row.
__global__ void k_agg(const __half* __restrict__ h, int N) {
    int warp = (blockIdx.x * blockDim.x + threadIdx.x) >> 5;
    int lane = threadIdx.x & 31;
    if (warp >= N) return;
    int beg = g_rowptr[warp], end = g_rowptr[warp + 1];
    float4 acc = make_float4(0.f, 0.f, 0.f, 0.f);
    int i = beg;
    for (; i + 1 < end; i += 2) {
        int s0 = __ldg(&g_col[i]), s1 = __ldg(&g_col[i + 1]);
        uint2 v0 = *(const uint2*)(h + (size_t)s0 * DIM + lane * 4);
        uint2 v1 = *(const uint2*)(h + (size_t)s1 * DIM + lane * 4);
        float2 a0 = __half22float2(*(__half2*)&v0.x);
        float2 a1 = __half22float2(*(__half2*)&v0.y);
        float2 b0 = __half22float2(*(__half2*)&v1.x);
        float2 b1 = __half22float2(*(__half2*)&v1.y);
        acc.x += a0.x + b0.x; acc.y += a0.y + b0.y;
        acc.z += a1.x + b1.x; acc.w += a1.y + b1.y;
    }
    if (i < end) {
        int s0 = __ldg(&g_col[i]);
        uint2 v0 = *(const uint2*)(h + (size_t)s0 * DIM + lane * 4);
        float2 a0 = __half22float2(*(__half2*)&v0.x);
        float2 a1 = __half22float2(*(__half2*)&v0.y);
        acc.x += a0.x; acc.y += a0.y; acc.z += a1.x; acc.w += a1.y;
    }
    int deg = end - beg;
    float inv = 1.0f / (float)(deg > 0 ? deg : 1);
    uint2 hi, lo;
    split2(acc.x * inv, acc.y * inv, hi.x, lo.x);
    split2(acc.z * inv, acc.w * inv, hi.y, lo.y);
    size_t off = (size_t)warp * DIM + lane * 4;
    *(uint2*)(g_aggHi + off) = hi;
    *(uint2*)(g_aggLo + off) = lo;
}

// ---------------- tensor-core fused dual GEMM --------------------------------
// out = relu(A@Wl + H@Wr + bias); operands pre-split bf16 hi/lo in global.
// 3-product accumulation: hi*hi + hi*lo + lo*hi  (~1e-5 accuracy).
// Epilogue emits fp16 (for gather/readout) + bf16 hi/lo (next GEMM H operand).
__device__ __forceinline__ void mma_bf16(float* c, const unsigned* a, const unsigned* b) {
    asm volatile(
        "mma.sync.aligned.m16n8k16.row.col.f32.bf16.bf16.f32 "
        "{%0,%1,%2,%3}, {%4,%5,%6,%7}, {%8,%9}, {%0,%1,%2,%3};\n"
        : "+f"(c[0]), "+f"(c[1]), "+f"(c[2]), "+f"(c[3])
        : "r"(a[0]), "r"(a[1]), "r"(a[2]), "r"(a[3]), "r"(b[0]), "r"(b[1]));
}

__global__ void __launch_bounds__(256)
k_gemm_tc(const bf16* __restrict__ Ahi, const bf16* __restrict__ Alo,
          const bf16* __restrict__ Hhi, const bf16* __restrict__ Hlo,
          const bf16* __restrict__ WtHi, const bf16* __restrict__ WtLo,
          const float* __restrict__ bias, __half* __restrict__ outF,
          bf16* __restrict__ outHi, bf16* __restrict__ outLo, int M)
{
    __shared__ __align__(16) bf16 sAhi[128][36], sAlo[128][36];
    __shared__ __align__(16) bf16 sWhi[128][36], sWlo[128][36];

    const int tid  = threadIdx.x;
    const int lane = tid & 31, warp = tid >> 5;
    const int wm = warp & 3, wn = warp >> 2;   // 4 x 2 warp grid
    const int g  = lane >> 2, t = lane & 3;
    const int row0 = blockIdx.x * 128;

    float acc[2][8][4];
    #pragma unroll
    for (int a = 0; a < 2; a++)
        #pragma unroll
        for (int b = 0; b < 8; b++)
            #pragma unroll
            for (int c = 0; c < 4; c++) acc[a][b][c] = 0.f;

    for (int kc = 0; kc < 8; kc++) {
        const bf16* srcHi = (kc < 4) ? Ahi : Hhi;
        const bf16* srcLo = (kc < 4) ? Alo : Hlo;
        const bf16* wHi   = WtHi + ((kc < 4) ? 0 : DIM * DIM);
        const bf16* wLo   = WtLo + ((kc < 4) ? 0 : DIM * DIM);
        const int koff = (kc & 3) * 32;

        #pragma unroll
        for (int j = 0; j < 2; j++) {
            int i = tid + j * 256;            // 0..511 uint4 slots
            int r = i >> 2, k8 = (i & 3) * 8;
            int gr = row0 + r;
            uint4 vh = make_uint4(0u,0u,0u,0u), vl = vh;
            if (gr < M) {
                size_t off = (size_t)gr * DIM + koff + k8;
                vh = *(const uint4*)(srcHi + off);
                vl = *(const uint4*)(srcLo + off);
            }
            *(uint2*)&sAhi[r][k8]     = make_uint2(vh.x, vh.y);
            *(uint2*)&sAhi[r][k8 + 4] = make_uint2(vh.z, vh.w);
            *(uint2*)&sAlo[r][k8]     = make_uint2(vl.x, vl.y);
            *(uint2*)&sAlo[r][k8 + 4] = make_uint2(vl.z, vl.w);
        }
        #pragma unroll
        for (int j = 0; j < 2; j++) {
            int i = tid + j * 256;
            int n = i >> 2, k8 = (i & 3) * 8;
            size_t off = (size_t)n * DIM + koff + k8;
            uint4 vh = *(const uint4*)(wHi + off);
            uint4 vl = *(const uint4*)(wLo + off);
            *(uint2*)&sWhi[n][k8]     = make_uint2(vh.x, vh.y);
            *(uint2*)&sWhi[n][k8 + 4] = make_uint2(vh.z, vh.w);
            *(uint2*)&sWlo[n][k8]     = make_uint2(vl.x, vl.y);
            *(uint2*)&sWlo[n][k8 + 4] = make_uint2(vl.z, vl.w);
        }
        __syncthreads();

        #pragma unroll
        for (int k0 = 0; k0 < 32; k0 += 16) {
            unsigned ahi[2][4], alo[2][4];
            #pragma unroll
            for (int mt = 0; mt < 2; mt++) {
                int rm = wm * 32 + mt * 16;
                ahi[mt][0] = *(const unsigned*)&sAhi[rm + g    ][k0 + 2 * t];
                ahi[mt][1] = *(const unsigned*)&sAhi[rm + 8 + g][k0 + 2 * t];
                ahi[mt][2] = *(const unsigned*)&sAhi[rm + g    ][k0 + 2 * t + 8];
                ahi[mt][3] = *(const unsigned*)&sAhi[rm + 8 + g][k0 + 2 * t + 8];
                alo[mt][0] = *(const unsigned*)&sAlo[rm + g    ][k0 + 2 * t];
                alo[mt][1] = *(const unsigned*)&sAlo[rm + 8 + g][k0 + 2 * t];
                alo[mt][2] = *(const unsigned*)&sAlo[rm + g    ][k0 + 2 * t + 8];
                alo[mt][3] = *(const unsigned*)&sAlo[rm + 8 + g][k0 + 2 * t + 8];
            }
            #pragma unroll
            for (int nt = 0; nt < 8; nt++) {
                int cn = wn * 64 + nt * 8 + g;
                unsigned bhi[2], blo[2];
                bhi[0] = *(const unsigned*)&sWhi[cn][k0 + 2 * t];
                bhi[1] = *(const unsigned*)&sWhi[cn][k0 + 2 * t + 8];
                blo[0] = *(const unsigned*)&sWlo[cn][k0 + 2 * t];
                blo[1] = *(const unsigned*)&sWlo[cn][k0 + 2 * t + 8];
                #pragma unroll
                for (int mt = 0; mt < 2; mt++) {
                    mma_bf16(acc[mt][nt], ahi[mt], bhi);
                    mma_bf16(acc[mt][nt], ahi[mt], blo);
                    mma_bf16(acc[mt][nt], alo[mt], bhi);
                }
            }
        }
        __syncthreads();
    }

    // epilogue: + bias, relu; store fp16 + bf16 hi/lo
    #pragma unroll
    for (int mt = 0; mt < 2; mt++) {
        int r0 = row0 + wm * 32 + mt * 16 + g;
        #pragma unroll
        for (int nt = 0; nt < 8; nt++) {
            int c = wn * 64 + nt * 8 + 2 * t;
            float b0 = __ldg(bias + c), b1 = __ldg(bias + c + 1);
            #pragma unroll
            for (int half = 0; half < 2; half++) {
                int rr = r0 + half * 8;
                if (rr < M) {
                    float ox = fmaxf(acc[mt][nt][2 * half]     + b0, 0.f);
                    float oy = fmaxf(acc[mt][nt][2 * half + 1] + b1, 0.f);
                    size_t off = (size_t)rr * DIM + c;
                    *(__half2*)(outF + off) = __floats2half2_rn(ox, oy);
                    unsigned hi, lo;
                    split2(ox, oy, hi, lo);
                    *(unsigned*)(outHi + off) = hi;
                    *(unsigned*)(outLo + off) = lo;
                }
            }
        }
    }
}

// ---------------- per-graph boundaries (batch is sorted) --------------------
__global__ void k_bounds(const void* __restrict__ batch, int n) {
    int g = blockIdx.x * blockDim.x + threadIdx.x;
    if (g > NG) return;
    int lo = 0, hi = n;
    while (lo < hi) {
        int mid = (lo + hi) >> 1;
        if (idx_at(batch, mid) < (long long)g) lo = mid + 1; else hi = mid;
    }
    g_gstart[g] = lo;
}

// ---------------- meanmax readout: one block per graph, fp16 input ----------
__global__ void k_readout(const __half* __restrict__ h, float* __restrict__ out) {
    int g = blockIdx.x;
    int c = threadIdx.x;                 // 0..127
    int s = g_gstart[g], e = g_gstart[g + 1];
    float sum = 0.f, mx = 0.f;           // post-relu values >= 0; empty -> 0
    for (int n = s; n < e; n++) {
        float v = __half2float(__ldg(h + (size_t)n * DIM + c));
        sum += v;
        mx = fmaxf(mx, v);
    }
    out[g * (2 * DIM) + c]       = sum / fmaxf((float)(e - s), 1.f);
    out[g * (2 * DIM) + DIM + c] = mx;
}

// ---------------- launcher ---------------------------------------------------
extern "C" void kernel_launch(void* const* d_in, const int* in_sizes, int n_in,
                              void* d_out, int out_size)
{
    const float* x     = (const float*)d_in[0];
    const void*  ei    = d_in[1];
    const void*  batch = d_in[2];
    const float* Wl0 = (const float*)d_in[3];
    const float* bl0 = (const float*)d_in[4];
    const float* Wr0 = (const float*)d_in[5];
    const float* Wl1 = (const float*)d_in[6];
    const float* bl1 = (const float*)d_in[7];
    const float* Wr1 = (const float*)d_in[8];
    const float* Wl2 = (const float*)d_in[9];
    const float* bl2 = (const float*)d_in[10];
    const float* Wr2 = (const float*)d_in[11];
    float* out = (float*)d_out;

    const int N = in_sizes[0] / DIM;     // 50000
    const int E = in_sizes[1] / 2;       // 800000

    __half *xf, *hfA, *hfB;
    bf16 *aggHi, *aggLo, *h0Hi, *h0Lo, *h1Hi, *h1Lo, *h2Hi, *h2Lo, *wtHi, *wtLo;
    cudaGetSymbolAddress((void**)&xf,  g_xf);
    cudaGetSymbolAddress((void**)&hfA, g_hfA);
    cudaGetSymbolAddress((void**)&hfB, g_hfB);
    cudaGetSymbolAddress((void**)&aggHi, g_aggHi);
    cudaGetSymbolAddress((void**)&aggLo, g_aggLo);
    cudaGetSymbolAddress((void**)&h0Hi, g_h0Hi);
    cudaGetSymbolAddress((void**)&h0Lo, g_h0Lo);
    cudaGetSymbolAddress((void**)&h1Hi, g_h1Hi);
    cudaGetSymbolAddress((void**)&h1Lo, g_h1Lo);
    cudaGetSymbolAddress((void**)&h2Hi, g_h2Hi);
    cudaGetSymbolAddress((void**)&h2Lo, g_h2Lo);
    cudaGetSymbolAddress((void**)&wtHi, g_wtHi);
    cudaGetSymbolAddress((void**)&wtLo, g_wtLo);

    const int nb = (N + 255) / 256;

    k_init  <<<(NN + 255) / 256, 256>>>();
    k_detect<<<1, 256>>>((const int*)ei, 2 * E);
    k_count <<<(E + 255) / 256, 256>>>(ei, E);
    k_bsum  <<<nb, 256>>>(N);
    k_bscan <<<1, 256>>>(nb, N);
    k_rowptr<<<nb, 256>>>(N);
    k_fill  <<<(E + 255) / 256, 256>>>(ei, E);

    k_prepx <<<(N * 32 + 255) / 256, 256>>>(x, N * 32);
    {
        dim3 gw((DIM * DIM + 255) / 256, 6);
        k_prepw<<<gw, 256>>>(Wl0, Wr0, Wl1, Wr1, Wl2, Wr2);
    }

    const int aggGrid  = (N * 32 + 255) / 256;    // one warp per node
    const int gemmGrid = (N + 127) / 128;

    // layer 0: A = agg(x) [fp16 gather], H = x (pre-split)
    k_agg    <<<aggGrid, 256>>>(xf, N);
    k_gemm_tc<<<gemmGrid, 256>>>(aggHi, aggLo, h0Hi, h0Lo,
                                 wtHi + 0 * DIM * DIM, wtLo + 0 * DIM * DIM,
                                 bl0, hfA, h1Hi, h1Lo, N);
    // layer 1
    k_agg    <<<aggGrid, 256>>>(hfA, N);
    k_gemm_tc<<<gemmGrid, 256>>>(aggHi, aggLo, h1Hi, h1Lo,
                                 wtHi + 2 * DIM * DIM, wtLo + 2 * DIM * DIM,
                                 bl1, hfB, h2Hi, h2Lo, N);
    // layer 2
    k_agg    <<<aggGrid, 256>>>(hfB, N);
    k_gemm_tc<<<gemmGrid, 256>>>(aggHi, aggLo, h2Hi, h2Lo,
                                 wtHi + 4 * DIM * DIM, wtLo + 4 * DIM * DIM,
                                 bl2, hfA, h1Hi, h1Lo, N);

    k_bounds <<<1, 512>>>(batch, N);
    k_readout<<<NG, DIM>>>(hfA, out);
}